// round 7
// baseline (speedup 1.0000x reference)
#include <cuda_runtime.h>
#include <cuda_fp16.h>
#include <cstdint>
#include <cstddef>

#define B_  4
#define C_  256
#define CQ_ 32
#define N_  4096
#define JT  128             // j tile per CTA
#define IT  128             // i tile per mainloop step
#define NIT (N_ / IT)       // 32
#define NTHR 512            // 16 warps
#define KSCALE 0.09016844005556021f   // (1/16) * log2(e)

// ---------------- scratch (device globals: allocation-free, 10 MB) ---------
// d_f: [b][n][q] Wq (query) projection -- the softmax/contraction index i side
// d_g: [b][n][q] Wk (key)   projection -- the output index j side
__device__ __half d_f[(size_t)B_ * N_ * CQ_];
__device__ __half d_g[(size_t)B_ * N_ * CQ_];
__device__ __half d_v[(size_t)B_ * C_ * N_];    // [b][c][n] values

__device__ __forceinline__ float ex2f(float x) {
    float y; asm("ex2.approx.f32 %0, %1;" : "=f"(y) : "f"(x)); return y;
}
__device__ __forceinline__ void mma_f16(float* d, const uint32_t* a,
                                        const uint32_t* b) {
    asm volatile(
        "mma.sync.aligned.m16n8k16.row.col.f32.f16.f16.f32 "
        "{%0,%1,%2,%3}, {%4,%5,%6,%7}, {%8,%9}, {%0,%1,%2,%3};"
        : "+f"(d[0]), "+f"(d[1]), "+f"(d[2]), "+f"(d[3])
        : "r"(a[0]), "r"(a[1]), "r"(a[2]), "r"(a[3]), "r"(b[0]), "r"(b[1]));
}
__device__ __forceinline__ uint32_t packh2(float a, float b) {
    __half2 p = __floats2half2_rn(a, b);
    return *reinterpret_cast<uint32_t*>(&p);
}

// --------------------------- SMEM layout (bytes) ---------------------------
// f/g tiles: [row][32 fp16], row stride 80 B
// V tile:    [256 c][128 i fp16], row stride 272 B
// P tile:    [128 j][128 i fp16], row stride 272 B
#define GSTR 80
#define VSTR 272
#define OFF_G    0                       // 128*80   = 10240
#define OFF_F    10240                   // 128*80   = 10240
#define OFF_V    20480                   // 256*272  = 69632
#define OFF_P    90112                   // 128*272  = 34816
#define OFF_LRED 124928                  // 16*16*4 = 1024
#define OFF_RINV 125952                  // 128*4
#define SMEM_TOTAL 126464

// =================== kernel 1a: f/g projection (fp32 FFMA) ================
// Y[b][n][q] (fp16, transposed) = W[q][c] @ x[b][c][n]
__global__ void proj_fg_kernel(const float* __restrict__ W,
                               const float* __restrict__ x, int which) {
    __half* Y = which ? d_g : d_f;
    const int b  = blockIdx.z;
    const int n0 = blockIdx.x * 128;
    const float* X = x + (size_t)b * C_ * N_;

    __shared__ float Ws[32][33];
    __shared__ float Xs[32][128];

    const int tid = threadIdx.x;
    const int r0 = (tid >> 5) << 2;
    const int c0 = (tid & 31) << 2;

    float acc[4][4] = {};
    for (int kk = 0; kk < C_; kk += 32) {
        #pragma unroll
        for (int it = 0; it < 4; ++it) {
            int e = tid + 256 * it;
            int r = e >> 5, cc = e & 31;
            Ws[r][cc] = W[(size_t)r * C_ + kk + cc];
        }
        #pragma unroll
        for (int it = 0; it < 4; ++it) {
            int e = tid + 256 * it;
            int r = e >> 5, c4 = (e & 31) << 2;
            *reinterpret_cast<float4*>(&Xs[r][c4]) =
                *reinterpret_cast<const float4*>(&X[(size_t)(kk + r) * N_ + n0 + c4]);
        }
        __syncthreads();
        #pragma unroll
        for (int k = 0; k < 32; ++k) {
            float4 xv = *reinterpret_cast<const float4*>(&Xs[k][c0]);
            #pragma unroll
            for (int i = 0; i < 4; ++i) {
                float w = Ws[r0 + i][k];
                acc[i][0] = fmaf(w, xv.x, acc[i][0]);
                acc[i][1] = fmaf(w, xv.y, acc[i][1]);
                acc[i][2] = fmaf(w, xv.z, acc[i][2]);
                acc[i][3] = fmaf(w, xv.w, acc[i][3]);
            }
        }
        __syncthreads();
    }
    #pragma unroll
    for (int k = 0; k < 4; ++k) {   // transposed fp16 write: [n][q]
        int n = n0 + c0 + k;
        uint2 w2 = make_uint2(packh2(acc[0][k], acc[1][k]),
                              packh2(acc[2][k], acc[3][k]));
        *reinterpret_cast<uint2*>(&Y[((size_t)b * N_ + n) * CQ_ + r0]) = w2;
    }
}

// =================== kernel 1b: v projection (fp32 FFMA) ==================
__global__ void proj_v_kernel(const float* __restrict__ W,
                              const float* __restrict__ x) {
    const int b  = blockIdx.z;
    const int n0 = blockIdx.x * 128;
    const int m0 = blockIdx.y * 32;
    const float* X = x + (size_t)b * C_ * N_;

    __shared__ float Ws[32][33];
    __shared__ float Xs[32][128];

    const int tid = threadIdx.x;
    const int r0 = (tid >> 5) << 2;
    const int c0 = (tid & 31) << 2;

    float acc[4][4] = {};
    for (int kk = 0; kk < C_; kk += 32) {
        #pragma unroll
        for (int it = 0; it < 4; ++it) {
            int e = tid + 256 * it;
            int r = e >> 5, cc = e & 31;
            Ws[r][cc] = W[(size_t)(m0 + r) * C_ + kk + cc];
        }
        #pragma unroll
        for (int it = 0; it < 4; ++it) {
            int e = tid + 256 * it;
            int r = e >> 5, c4 = (e & 31) << 2;
            *reinterpret_cast<float4*>(&Xs[r][c4]) =
                *reinterpret_cast<const float4*>(&X[(size_t)(kk + r) * N_ + n0 + c4]);
        }
        __syncthreads();
        #pragma unroll
        for (int k = 0; k < 32; ++k) {
            float4 xv = *reinterpret_cast<const float4*>(&Xs[k][c0]);
            #pragma unroll
            for (int i = 0; i < 4; ++i) {
                float w = Ws[r0 + i][k];
                acc[i][0] = fmaf(w, xv.x, acc[i][0]);
                acc[i][1] = fmaf(w, xv.y, acc[i][1]);
                acc[i][2] = fmaf(w, xv.z, acc[i][2]);
                acc[i][3] = fmaf(w, xv.w, acc[i][3]);
            }
        }
        __syncthreads();
    }
    #pragma unroll
    for (int i = 0; i < 4; ++i) {
        uint2 w2 = make_uint2(packh2(acc[i][0], acc[i][1]),
                              packh2(acc[i][2], acc[i][3]));
        *reinterpret_cast<uint2*>(&d_v[((size_t)b * C_ + m0 + r0 + i) * N_ + n0 + c0]) = w2;
    }
}

// ============ kernel 2: fused scores+softmax+out via mma.sync =============
// Per CTA: batch b, 128-j tile. 16 warps, 512 threads.
//   Phase A: warps w=2s+h share j strip [16s,16s+16); h picks 64-i half.
//            S[j][i] = sum_q g[j][q] f[i][q]; p=ex2(S*KSCALE) -> fp16 P[j][i].
//   Phase B: warp w owns c strip [16w,16w+16) x 128 j; fp32 accum in regs
//            across all 32 i-tiles (oacc[16][4] = 64 regs).
__global__ void __launch_bounds__(NTHR, 1)
fused_attn_mma(float* __restrict__ out) {
    extern __shared__ __align__(16) char smem[];
    const int b  = blockIdx.y;
    const int jb = blockIdx.x * JT;
    const int tid  = threadIdx.x;
    const int lane = tid & 31, warp = tid >> 5;
    const int lr = lane >> 2, lm = lane & 3;
    const int jw = (warp >> 1) * 16;    // phase-A j strip (2 warps share)
    const int ih = warp & 1;            // phase-A i half (0: 0-63, 1: 64-127)
    const int cw = warp * 16;           // phase-B c strip

    const __half* fB = d_f + (size_t)b * N_ * CQ_;
    const __half* gB = d_g + (size_t)b * N_ * CQ_;
    const __half* vB = d_v + (size_t)b * C_ * N_;

    // ---- g (key) tile once: [j][32 q] fp16, 64B data per 80B row ----
    {
        int row = tid >> 2, ch = tid & 3;              // 512 x 16B
        uint4 w = *reinterpret_cast<const uint4*>(&gB[(size_t)(jb + row) * CQ_ + ch * 8]);
        *reinterpret_cast<uint4*>(smem + OFF_G + row * GSTR + ch * 16) = w;
    }

    float oacc[16][4];
    #pragma unroll
    for (int n = 0; n < 16; ++n)
        #pragma unroll
        for (int k = 0; k < 4; ++k) oacc[n][k] = 0.f;
    float lsum0 = 0.f, lsum1 = 0.f;

    for (int t = 0; t < NIT; ++t) {
        const int i0 = t * IT;
        if (t > 0) __syncthreads();               // phase B done with P/V/f

        // f (query) tile: [i][32 q], 512 x 16B
        {
            int row = tid >> 2, ch = tid & 3;
            uint4 w = *reinterpret_cast<const uint4*>(&fB[(size_t)(i0 + row) * CQ_ + ch * 8]);
            *reinterpret_cast<uint4*>(smem + OFF_F + row * GSTR + ch * 16) = w;
        }
        // V tile: [256 c][128 i] fp16, 4096 x 16B
        #pragma unroll
        for (int it = 0; it < 8; ++it) {
            int id = tid + NTHR * it;
            int row = id >> 4, ch = id & 15;
            uint4 w = *reinterpret_cast<const uint4*>(&vB[(size_t)row * N_ + i0 + ch * 8]);
            *reinterpret_cast<uint4*>(smem + OFF_V + row * VSTR + ch * 16) = w;
        }
        __syncthreads();                          // tiles (and g at t=0) visible

        // ---------------- phase A: S strip (16 j x 64 i) + exp -> P -------
        {
            float sacc[8][4] = {};
            #pragma unroll
            for (int kk = 0; kk < 2; ++kk) {      // q chunks of 16
                uint32_t ag[4];
                const char* ga = smem + OFF_G + (jw + lr) * GSTR + kk * 32 + lm * 4;
                ag[0] = *(const uint32_t*)ga;
                ag[1] = *(const uint32_t*)(ga + 8 * GSTR);
                ag[2] = *(const uint32_t*)(ga + 16);
                ag[3] = *(const uint32_t*)(ga + 8 * GSTR + 16);
                #pragma unroll
                for (int n = 0; n < 8; ++n) {
                    uint32_t bf[2];
                    const char* fa = smem + OFF_F + (ih * 64 + n * 8 + lr) * GSTR
                                     + kk * 32 + lm * 4;
                    bf[0] = *(const uint32_t*)fa;
                    bf[1] = *(const uint32_t*)(fa + 16);
                    mma_f16(sacc[n], ag, bf);
                }
            }
            #pragma unroll
            for (int n = 0; n < 8; ++n) {
                const int ic = ih * 64 + n * 8 + lm * 2;  // i column
                float p0 = ex2f(sacc[n][0] * KSCALE);
                float p1 = ex2f(sacc[n][1] * KSCALE);
                float p2 = ex2f(sacc[n][2] * KSCALE);
                float p3 = ex2f(sacc[n][3] * KSCALE);
                lsum0 += p0 + p1;  lsum1 += p2 + p3;
                *(uint32_t*)(smem + OFF_P + (jw + lr) * VSTR + ic * 2)     = packh2(p0, p1);
                *(uint32_t*)(smem + OFF_P + (jw + lr + 8) * VSTR + ic * 2) = packh2(p2, p3);
            }
        }
        __syncthreads();                          // P visible

        // ---------------- phase B: O += V * P (16 c x 128 j) --------------
        #pragma unroll
        for (int kk = 0; kk < 8; ++kk) {          // i chunks of 16
            uint32_t af[4];
            const char* aa = smem + OFF_V + (cw + lr) * VSTR + kk * 32 + lm * 4;
            af[0] = *(const uint32_t*)aa;
            af[1] = *(const uint32_t*)(aa + 8 * VSTR);
            af[2] = *(const uint32_t*)(aa + 16);
            af[3] = *(const uint32_t*)(aa + 8 * VSTR + 16);
            #pragma unroll
            for (int n = 0; n < 16; ++n) {        // j blocks of 8
                uint32_t bf[2];
                const char* ba = smem + OFF_P + (n * 8 + lr) * VSTR + kk * 32 + lm * 4;
                bf[0] = *(const uint32_t*)ba;
                bf[1] = *(const uint32_t*)(ba + 16);
                mma_f16(oacc[n], af, bf);
            }
        }
    }

    // ---- row sums -> rinv ----
    // lane sums cover this warp's 64-i half of rows (jw+lr) and (jw+lr+8).
    lsum0 += __shfl_xor_sync(0xffffffffu, lsum0, 1);
    lsum0 += __shfl_xor_sync(0xffffffffu, lsum0, 2);
    lsum1 += __shfl_xor_sync(0xffffffffu, lsum1, 1);
    lsum1 += __shfl_xor_sync(0xffffffffu, lsum1, 2);
    __syncthreads();                               // phase B done reading P
    if (lm == 0) {
        float* lred = reinterpret_cast<float*>(smem + OFF_LRED);
        lred[warp * 16 + lr]     = lsum0;          // [warp][local row]
        lred[warp * 16 + lr + 8] = lsum1;
    }
    __syncthreads();
    if (tid < 128) {
        const float* lred = reinterpret_cast<const float*>(smem + OFF_LRED);
        int s = tid >> 4, jl = tid & 15;           // strip s = warps 2s, 2s+1
        reinterpret_cast<float*>(smem + OFF_RINV)[tid] =
            1.0f / (lred[(2 * s) * 16 + jl] + lred[(2 * s + 1) * 16 + jl]);
    }
    __syncthreads();
    const float* rinv = reinterpret_cast<const float*>(smem + OFF_RINV);

    // ---- write O ----
    #pragma unroll
    for (int n = 0; n < 16; ++n) {
        const int c = cw + lr;
        const int j = n * 8 + lm * 2;
        const float r0 = rinv[j], r1 = rinv[j + 1];
        float2 o0 = make_float2(oacc[n][0] * r0, oacc[n][1] * r1);
        float2 o1 = make_float2(oacc[n][2] * r0, oacc[n][3] * r1);
        *reinterpret_cast<float2*>(&out[((size_t)b * C_ + c) * N_ + jb + j])     = o0;
        *reinterpret_cast<float2*>(&out[((size_t)b * C_ + c + 8) * N_ + jb + j]) = o1;
    }
}

// ---------------------------------------------------------------------------
extern "C" void kernel_launch(void* const* d_in, const int* in_sizes, int n_in,
                              void* d_out, int out_size) {
    (void)in_sizes; (void)n_in; (void)out_size;
    const float* x  = (const float*)d_in[0];
    const float* Wq = (const float*)d_in[1];
    const float* Wk = (const float*)d_in[2];
    const float* Wv = (const float*)d_in[3];
    float* out = (float*)d_out;

    static int smem_set = 0;
    if (!smem_set) {
        cudaFuncSetAttribute(fused_attn_mma,
                             cudaFuncAttributeMaxDynamicSharedMemorySize, SMEM_TOTAL);
        smem_set = 1;
    }

    dim3 blk(256);
    // d_f (i / softmax side) takes Wq (query, f_ref);
    // d_g (j / output side)  takes Wk (key,   g_ref).
    proj_fg_kernel<<<dim3(N_ / 128, 1, B_), blk>>>(Wq, x, 0);   // Wq -> d_f
    proj_fg_kernel<<<dim3(N_ / 128, 1, B_), blk>>>(Wk, x, 1);   // Wk -> d_g
    proj_v_kernel<<<dim3(N_ / 128, C_ / 32, B_), blk>>>(Wv, x);
    fused_attn_mma<<<dim3(N_ / JT, B_), NTHR, SMEM_TOTAL>>>(out);
}